// round 6
// baseline (speedup 1.0000x reference)
#include <cuda_runtime.h>
#include <cuda_bf16.h>
#include <cstdint>

#define NB 32
#define NM 2048
#define ND 1024
#define NK 64
#define BM (NB*NM)   // 65536 rows total

// ---------------- scratch (device globals; no allocs allowed) ----------------
__device__ __nv_bfloat16 g_x16[(size_t)BM * ND];       // 128 MB bf16(x) RAW (not normalized)
__device__ __nv_bfloat16 g_w16[NK * ND];               // W in bf16
__device__ __nv_bfloat16 g_a[(size_t)BM * NK];         // p[m,k] * inv_m  (bf16)
__device__ float         g_asum[NB * NK];              // sum_m p[b,m,k]  (unscaled)
__device__ float         g_vraw[(size_t)2 * NB * NK * ND]; // 2 M-split partials of A'^T X

// ---------------- helpers ----------------
static __device__ __forceinline__ unsigned s2u(const void* p) {
    return (unsigned)__cvta_generic_to_shared(p);
}
static __device__ __forceinline__ void cp16(unsigned dst, const void* src) {
    asm volatile("cp.async.cg.shared.global [%0], [%1], 16;\n" :: "r"(dst), "l"(src));
}
static __device__ __forceinline__ void cp_commit() {
    asm volatile("cp.async.commit_group;\n");
}
template<int N> static __device__ __forceinline__ void cp_wait() {
    asm volatile("cp.async.wait_group %0;\n" :: "n"(N));
}
static __device__ __forceinline__ void ldsm_x4(unsigned& r0, unsigned& r1, unsigned& r2, unsigned& r3, unsigned a) {
    asm volatile("ldmatrix.sync.aligned.m8n8.x4.shared.b16 {%0,%1,%2,%3}, [%4];"
                 : "=r"(r0), "=r"(r1), "=r"(r2), "=r"(r3) : "r"(a));
}
static __device__ __forceinline__ void ldsm_x4t(unsigned& r0, unsigned& r1, unsigned& r2, unsigned& r3, unsigned a) {
    asm volatile("ldmatrix.sync.aligned.m8n8.x4.trans.shared.b16 {%0,%1,%2,%3}, [%4];"
                 : "=r"(r0), "=r"(r1), "=r"(r2), "=r"(r3) : "r"(a));
}
static __device__ __forceinline__ void ldsm_x2(unsigned& r0, unsigned& r1, unsigned a) {
    asm volatile("ldmatrix.sync.aligned.m8n8.x2.shared.b16 {%0,%1}, [%2];"
                 : "=r"(r0), "=r"(r1) : "r"(a));
}
static __device__ __forceinline__ void ldsm_x2t(unsigned& r0, unsigned& r1, unsigned a) {
    asm volatile("ldmatrix.sync.aligned.m8n8.x2.trans.shared.b16 {%0,%1}, [%2];"
                 : "=r"(r0), "=r"(r1) : "r"(a));
}
static __device__ __forceinline__ void mma16816(float* c,
        unsigned a0, unsigned a1, unsigned a2, unsigned a3, unsigned b0, unsigned b1) {
    asm volatile("mma.sync.aligned.m16n8k16.row.col.f32.bf16.bf16.f32 "
                 "{%0,%1,%2,%3}, {%4,%5,%6,%7}, {%8,%9}, {%0,%1,%2,%3};"
                 : "+f"(c[0]), "+f"(c[1]), "+f"(c[2]), "+f"(c[3])
                 : "r"(a0), "r"(a1), "r"(a2), "r"(a3), "r"(b0), "r"(b1));
}

// ---------------- kernel 0: W -> bf16, zero a_sum ----------------
__global__ __launch_bounds__(256) void k_wconv(const float* __restrict__ W) {
    int i = blockIdx.x * 256 + threadIdx.x;       // grid 256 -> exactly NK*ND
    g_w16[i] = __float2bfloat16_rn(W[i]);
    if (i < NB * NK) g_asum[i] = 0.f;
}

// ============ fused: x->bf16 + logits GEMM + row-norm + softmax + a_sum ============
// 128 rows per block (grid 512). x streamed in d-chunks of 64: LDG fp32 -> reg,
// cvt to bf16 in smem (+ raw store to g_x16), MMA vs W, sum-of-squares alongside.
// Loop body ordered cvt -> ldg -> MMA so the DRAM burst drains under the compute.
//
// dyn smem layout (bytes):
//   xs[2] [128][72] bf16  @ 0      36864
//   wt[2] [64][72]  bf16  @ 36864  18432
//   lg    [128][66] f32   @ 0      (alias xs, used after GEMM)   33792
//   ssrow [128]     f32   @ 55296    512
//   sas   [64]      f32   @ 55808    256
#define NL_SMEM 56064
__global__ __launch_bounds__(256, 2) void k_nl(const float* __restrict__ x) {
    extern __shared__ __align__(16) unsigned char dsm[];
    __nv_bfloat16* xs[2] = { (__nv_bfloat16*)dsm, (__nv_bfloat16*)(dsm + 18432) };
    __nv_bfloat16* wt[2] = { (__nv_bfloat16*)(dsm + 36864), (__nv_bfloat16*)(dsm + 46080) };
    float* lg    = (float*)dsm;
    float* ssrow = (float*)(dsm + 55296);
    float* sas   = (float*)(dsm + 55808);

    const int tid = threadIdx.x, lane = tid & 31, warp = tid >> 5;
    const int m0 = blockIdx.x * 128;
    const int b  = m0 >> 11;

    if (tid < 64) sas[tid] = 0.f;

    const int xc = (tid & 15) * 4;      // float col within 64-wide chunk
    const int xg = tid >> 4;            // row group base (0..15)

    float4 xr[8];
    float ss[8];
#pragma unroll
    for (int i = 0; i < 8; i++) ss[i] = 0.f;

    float acc[8][4];
#pragma unroll
    for (int i = 0; i < 8; i++)
#pragma unroll
        for (int j = 0; j < 4; j++) acc[i][j] = 0.f;

    auto ldg_chunk = [&](int ch) {
#pragma unroll
        for (int it = 0; it < 8; it++) {
            int row = m0 + xg + 16 * it;
            xr[it] = *(const float4*)(x + (size_t)row * ND + ch * 64 + xc);
        }
    };
    auto cvt_chunk = [&](int ch, int s) {
#pragma unroll
        for (int it = 0; it < 8; it++) {
            int row = xg + 16 * it;
            float4 v = xr[it];
            ss[it] += v.x * v.x + v.y * v.y + v.z * v.z + v.w * v.w;
            __nv_bfloat162 h01, h23;
            h01.x = __float2bfloat16_rn(v.x);
            h01.y = __float2bfloat16_rn(v.y);
            h23.x = __float2bfloat16_rn(v.z);
            h23.y = __float2bfloat16_rn(v.w);
            uint2 u;
            u.x = *reinterpret_cast<unsigned*>(&h01);
            u.y = *reinterpret_cast<unsigned*>(&h23);
            *(uint2*)(xs[s] + row * 72 + xc) = u;
            *(uint2*)(g_x16 + (size_t)(m0 + row) * ND + ch * 64 + xc) = u;
        }
    };
    auto ldw_chunk = [&](int ch, int s) {
#pragma unroll
        for (int it = 0; it < 2; it++) {
            int idx = tid + it * 256;
            int r = idx >> 3, c = idx & 7;
            cp16(s2u(wt[s] + r * 72 + c * 8), g_w16 + (size_t)r * ND + ch * 64 + c * 8);
        }
        cp_commit();
    };

    // ---- prologue ----
    ldg_chunk(0);
    ldw_chunk(0, 0);
    ldw_chunk(1, 1);
    cvt_chunk(0, 0);
    ldg_chunk(1);
    cp_wait<1>();
    __syncthreads();

    const int ar = warp * 16;   // warp's 16 m-rows

    // ---- main loop over 16 d-chunks: cvt -> ldg (early DRAM burst) -> MMA ----
    for (int ch = 0; ch < 16; ch++) {
        const int s = ch & 1;
        if (ch < 15) cvt_chunk(ch + 1, s ^ 1);   // consumes xr, fills xs[s^1]
        if (ch < 14) ldg_chunk(ch + 2);          // refill xr; drains under MMA
#pragma unroll
        for (int ds = 0; ds < 4; ds++) {
            unsigned a0, a1, a2, a3;
            {
                int r = ar + (lane & 7) + ((lane >> 3) & 1) * 8;
                int c = ds * 16 + ((lane >> 4) & 1) * 8;
                ldsm_x4(a0, a1, a2, a3, s2u(xs[s] + r * 72 + c));
            }
#pragma unroll
            for (int nt = 0; nt < 8; nt++) {
                unsigned b0r, b1r;
                int r = nt * 8 + (lane & 7);
                int c = ds * 16 + ((lane >> 3) & 1) * 8;
                ldsm_x2(b0r, b1r, s2u(wt[s] + r * 72 + c));
                mma16816(acc[nt], a0, a1, a2, a3, b0r, b1r);
            }
        }
        __syncthreads();                 // all reads of xs[s], wt[s] complete
        if (ch < 14) { ldw_chunk(ch + 2, s); cp_wait<1>(); }
        else         cp_wait<0>();
        __syncthreads();                 // wt writes visible
    }

    // ---- row sum-of-squares reduction (16 lanes share a row) ----
#pragma unroll
    for (int it = 0; it < 8; it++) {
        float v = ss[it];
#pragma unroll
        for (int o = 8; o > 0; o >>= 1) v += __shfl_xor_sync(0xffffffffu, v, o);
        if ((lane & 15) == 0) ssrow[xg + 16 * it] = v;
    }
    // ---- dump logits (alias xs region; GEMM done) ----
#pragma unroll
    for (int nt = 0; nt < 8; nt++) {
        int r0 = ar + (lane >> 2);
        int c0 = nt * 8 + 2 * (lane & 3);
        lg[r0 * 66 + c0]           = acc[nt][0];
        lg[r0 * 66 + c0 + 1]       = acc[nt][1];
        lg[(r0 + 8) * 66 + c0]     = acc[nt][2];
        lg[(r0 + 8) * 66 + c0 + 1] = acc[nt][3];
    }
    __syncthreads();

    // ---- softmax: each warp does its 16 rows; lane owns cols (2l, 2l+1) ----
    float s0 = 0.f, s1 = 0.f;
    const int c0 = 2 * lane, c1 = 2 * lane + 1;
#pragma unroll 1
    for (int r = 0; r < 16; r++) {
        int rr = ar + r;
        float inv = 1.0f / fmaxf(sqrtf(ssrow[rr]), 1e-12f);
        float v0 = lg[rr * 66 + c0] * inv, v1 = lg[rr * 66 + c1] * inv;
        float mx = fmaxf(v0, v1);
#pragma unroll
        for (int o = 16; o > 0; o >>= 1) mx = fmaxf(mx, __shfl_xor_sync(0xffffffffu, mx, o));
        float e0 = expf(v0 - mx), e1 = expf(v1 - mx);
        float sm = e0 + e1;
#pragma unroll
        for (int o = 16; o > 0; o >>= 1) sm += __shfl_xor_sync(0xffffffffu, sm, o);
        float is = 1.0f / sm;
        float p0 = e0 * is, p1 = e1 * is;
        s0 += p0; s1 += p1;
        __nv_bfloat162 h;                    // store p * inv_m  (normalization folded in)
        h.x = __float2bfloat16_rn(p0 * inv);
        h.y = __float2bfloat16_rn(p1 * inv);
        ((__nv_bfloat162*)(g_a + (size_t)(m0 + rr) * NK))[lane] = h;
    }
    atomicAdd(&sas[c0], s0);
    atomicAdd(&sas[c1], s1);
    __syncthreads();
    if (tid < 64) atomicAdd(&g_asum[b * NK + tid], sas[tid]);
}

// ============ kernel: vlad partial[z][b] = A'(b, z-half)^T @ X(b, z-half) ============
// grid (8 d-tiles, 32 b, 2 m-splits); block computes [64 k x 128 d] over M=1024,
// with 2-stage cp.async double buffering. A' = p*inv, X = raw bf16(x).
#define VL_SMEM 53248
__global__ __launch_bounds__(256) void k_vlad() {
    extern __shared__ __align__(16) unsigned char dsm[];
    __nv_bfloat16* at[2] = { (__nv_bfloat16*)dsm,           (__nv_bfloat16*)(dsm + 9216) };
    __nv_bfloat16* xt[2] = { (__nv_bfloat16*)(dsm + 18432), (__nv_bfloat16*)(dsm + 35840) };

    const int tid = threadIdx.x, lane = tid & 31, warp = tid >> 5;
    const int b  = blockIdx.y;
    const int z  = blockIdx.z;
    const int d0 = blockIdx.x * 128;
    const int wk = (warp & 3) * 16;     // k-row base for this warp
    const int wd = (warp >> 2) * 64;    // d-col base within tile

    const size_t rowbase = (size_t)b * NM + (size_t)z * (NM / 2);

    float acc[8][4];
#pragma unroll
    for (int i = 0; i < 8; i++)
#pragma unroll
        for (int j = 0; j < 4; j++) acc[i][j] = 0.f;

    auto issue = [&](int mc, int s) {
        const size_t mrow = rowbase + mc * 64;
#pragma unroll
        for (int it = 0; it < 2; it++) {     // a tile: 64 m x 64 k
            int idx = tid + it * 256;
            int r = idx >> 3, c = idx & 7;
            cp16(s2u(at[s] + r * 72 + c * 8), g_a + (mrow + r) * NK + c * 8);
        }
#pragma unroll
        for (int it = 0; it < 4; it++) {     // x tile: 64 m x 128 d
            int idx = tid + it * 256;
            int r = idx >> 4, c = idx & 15;
            cp16(s2u(xt[s] + r * 136 + c * 8), g_x16 + (mrow + r) * ND + d0 + c * 8);
        }
        cp_commit();
    };

    issue(0, 0);
    for (int mc = 0; mc < 16; mc++) {
        if (mc + 1 < 16) { issue(mc + 1, (mc + 1) & 1); cp_wait<1>(); }
        else             { cp_wait<0>(); }
        __syncthreads();
        const int s = mc & 1;
#pragma unroll
        for (int ms = 0; ms < 4; ms++) {
            int mb = ms * 16;
            unsigned a0, a1, a2, a3;
            {   // A = a^T (k x m) from [m][k] storage -> ldmatrix.trans
                int i = lane & 7;
                int r = mb + i + ((lane >> 4) & 1) * 8;
                int c = wk + ((lane >> 3) & 1) * 8;
                ldsm_x4t(a0, a1, a2, a3, s2u(at[s] + r * 72 + c));
            }
#pragma unroll
            for (int nt = 0; nt < 8; nt++) {
                unsigned b0, b1;
                int i = lane & 7;
                int r = mb + i + ((lane >> 3) & 1) * 8;
                int c = wd + nt * 8;
                ldsm_x2t(b0, b1, s2u(xt[s] + r * 136 + c));
                mma16816(acc[nt], a0, a1, a2, a3, b0, b1);
            }
        }
        __syncthreads();
    }

    float* vb = g_vraw + ((size_t)z * NB + b) * NK * ND;
#pragma unroll
    for (int nt = 0; nt < 8; nt++) {
        int k0 = wk + (lane >> 2);
        int dd = d0 + wd + nt * 8 + 2 * (lane & 3);
        *(float2*)(vb + (size_t)k0 * ND + dd)       = make_float2(acc[nt][0], acc[nt][1]);
        *(float2*)(vb + (size_t)(k0 + 8) * ND + dd) = make_float2(acc[nt][2], acc[nt][3]);
    }
}

// ---------------- kernel: centroid subtract + intra-norm + global(1/8) ----------------
__global__ __launch_bounds__(256) void k_final(const float* __restrict__ cent,
                                               float* __restrict__ out) {
    const int bk = blockIdx.x;           // b*64 + k
    const int k  = bk & 63;
    const int tid = threadIdx.x, lane = tid & 31, warp = tid >> 5;
    const float* vr0 = g_vraw + (size_t)bk * ND;
    const float* vr1 = g_vraw + (size_t)NB * NK * ND + (size_t)bk * ND;
    const float* cp = cent + (size_t)k * ND;
    const float as = g_asum[bk];
    float v[4];
    float ss = 0.f;
#pragma unroll
    for (int i = 0; i < 4; i++) {
        int d = tid + i * 256;
        v[i] = vr0[d] + vr1[d] - as * cp[d];
        ss += v[i] * v[i];
    }
#pragma unroll
    for (int o = 16; o > 0; o >>= 1) ss += __shfl_xor_sync(0xffffffffu, ss, o);
    __shared__ float red[8];
    if (lane == 0) red[warp] = ss;
    __syncthreads();
    float tot = red[0] + red[1] + red[2] + red[3] + red[4] + red[5] + red[6] + red[7];
    // intra-normalize; global norm is exactly sqrt(64)=8 after intra-normalization
    float inv = 0.125f / fmaxf(sqrtf(tot), 1e-12f);
    float* op = out + (size_t)bk * ND;
#pragma unroll
    for (int i = 0; i < 4; i++) op[tid + i * 256] = v[i] * inv;
}

// ---------------- launch ----------------
extern "C" void kernel_launch(void* const* d_in, const int* in_sizes, int n_in,
                              void* d_out, int out_size) {
    const float* x    = (const float*)d_in[0];
    const float* W    = (const float*)d_in[1];
    const float* cent = (const float*)d_in[2];
    float* out = (float*)d_out;

    static int configured = 0;
    if (!configured) {
        cudaFuncSetAttribute(k_nl,   cudaFuncAttributeMaxDynamicSharedMemorySize, NL_SMEM);
        cudaFuncSetAttribute(k_vlad, cudaFuncAttributeMaxDynamicSharedMemorySize, VL_SMEM);
        configured = 1;
    }

    k_wconv<<<256, 256>>>(W);
    k_nl   <<<512, 256, NL_SMEM>>>(x);
    k_vlad <<<dim3(8, 32, 2), 256, VL_SMEM>>>();
    k_final<<<2048, 256>>>(cent, out);
}

// round 7
// speedup vs baseline: 1.0499x; 1.0499x over previous
#include <cuda_runtime.h>
#include <cuda_bf16.h>
#include <cstdint>

#define NB 32
#define NM 2048
#define ND 1024
#define NK 64
#define BM (NB*NM)   // 65536 rows total

// ---------------- scratch (device globals; no allocs allowed) ----------------
__device__ __nv_bfloat16 g_x16[(size_t)BM * ND];       // 128 MB bf16(x) RAW (not normalized)
__device__ __nv_bfloat16 g_w16[NK * ND];               // W in bf16, k-PERMUTED within 16-groups
__device__ __nv_bfloat16 g_a[(size_t)BM * NK];         // p[m,k] * inv_m  (bf16)
__device__ float         g_asum[NB * NK];              // sum_m p[b,m,k]  (unscaled)
__device__ float         g_vraw[(size_t)2 * NB * NK * ND]; // 2 M-split partials of A'^T X

// ---------------- helpers ----------------
static __device__ __forceinline__ unsigned s2u(const void* p) {
    return (unsigned)__cvta_generic_to_shared(p);
}
static __device__ __forceinline__ void cp16(unsigned dst, const void* src) {
    asm volatile("cp.async.cg.shared.global [%0], [%1], 16;\n" :: "r"(dst), "l"(src));
}
static __device__ __forceinline__ void cp_commit() {
    asm volatile("cp.async.commit_group;\n");
}
template<int N> static __device__ __forceinline__ void cp_wait() {
    asm volatile("cp.async.wait_group %0;\n" :: "n"(N));
}
static __device__ __forceinline__ void ldsm_x4(unsigned& r0, unsigned& r1, unsigned& r2, unsigned& r3, unsigned a) {
    asm volatile("ldmatrix.sync.aligned.m8n8.x4.shared.b16 {%0,%1,%2,%3}, [%4];"
                 : "=r"(r0), "=r"(r1), "=r"(r2), "=r"(r3) : "r"(a));
}
static __device__ __forceinline__ void ldsm_x4t(unsigned& r0, unsigned& r1, unsigned& r2, unsigned& r3, unsigned a) {
    asm volatile("ldmatrix.sync.aligned.m8n8.x4.trans.shared.b16 {%0,%1,%2,%3}, [%4];"
                 : "=r"(r0), "=r"(r1), "=r"(r2), "=r"(r3) : "r"(a));
}
static __device__ __forceinline__ void mma16816(float* c,
        unsigned a0, unsigned a1, unsigned a2, unsigned a3, unsigned b0, unsigned b1) {
    asm volatile("mma.sync.aligned.m16n8k16.row.col.f32.bf16.bf16.f32 "
                 "{%0,%1,%2,%3}, {%4,%5,%6,%7}, {%8,%9}, {%0,%1,%2,%3};"
                 : "+f"(c[0]), "+f"(c[1]), "+f"(c[2]), "+f"(c[3])
                 : "r"(a0), "r"(a1), "r"(a2), "r"(a3), "r"(b0), "r"(b1));
}
static __device__ __forceinline__ unsigned packbf(float a, float b) {
    __nv_bfloat162 h;
    h.x = __float2bfloat16_rn(a);
    h.y = __float2bfloat16_rn(b);
    return *reinterpret_cast<unsigned*>(&h);
}

// ---------------- kernel 0: W -> bf16 (k-permuted), zero a_sum ----------------
// Permutation within each 16-col group: logical j -> slot 2*(j>>2)+(j&1)+((j&2)?8:0).
// This matches the A-side register fragments built straight from float4 LDGs, so
// mma contracts identical (logical k) pairs on both operands.
__global__ __launch_bounds__(256) void k_wconv(const float* __restrict__ W) {
    int i = blockIdx.x * 256 + threadIdx.x;       // grid 256 -> exactly NK*ND
    int kl = i & (ND - 1);
    int j  = kl & 15;
    int sl = 2 * (j >> 2) + (j & 1) + ((j & 2) ? 8 : 0);
    int oc = (kl & ~15) | sl;
    g_w16[(i & ~(ND - 1)) | oc] = __float2bfloat16_rn(W[i]);
    if (i < NB * NK) g_asum[i] = 0.f;
}

// ============ fused: x->bf16 + logits GEMM + row-norm + softmax + a_sum ============
// 128 rows per block (grid 512). A-operand fragments built DIRECTLY from x LDG.128
// registers (no x smem, no A ldsm). Raw bf16 streamed to g_x16 from the same regs.
// W tiles double-buffered via cp.async, consumed with ldsm_x4 (2 nt per load).
//
// dyn smem layout (bytes):
//   wt[2] [64][72] bf16 @ 0      18432
//   lg    [128][66] f32 @ 18432  33792
//   ssrow [128]     f32 @ 52224    512
//   sas   [64]      f32 @ 52736    256
#define NL_SMEM 52992
__global__ __launch_bounds__(256, 2) void k_nl(const float* __restrict__ x) {
    extern __shared__ __align__(16) unsigned char dsm[];
    __nv_bfloat16* wt[2] = { (__nv_bfloat16*)dsm, (__nv_bfloat16*)(dsm + 9216) };
    float* lg    = (float*)(dsm + 18432);
    float* ssrow = (float*)(dsm + 52224);
    float* sas   = (float*)(dsm + 52736);

    const int tid = threadIdx.x, lane = tid & 31, warp = tid >> 5;
    const int m0 = blockIdx.x * 128;
    const int b  = m0 >> 11;

    if (tid < 64) sas[tid] = 0.f;

    const int gr = lane >> 2, q = lane & 3;
    const int ar = warp * 16;                       // warp's 16 m-rows
    const size_t row0 = (size_t)(m0 + ar + gr);     // lo row; hi row = row0 + 8

    float4 xr[2][4][2];
    float ss0 = 0.f, ss1 = 0.f;

    float acc[8][4];
#pragma unroll
    for (int i = 0; i < 8; i++)
#pragma unroll
        for (int j = 0; j < 4; j++) acc[i][j] = 0.f;

    auto ldw = [&](int ch, int s) {
#pragma unroll
        for (int it = 0; it < 2; it++) {
            int idx = tid + it * 256;
            int r = idx >> 3, c = idx & 7;
            cp16(s2u(wt[s] + r * 72 + c * 8), g_w16 + (size_t)r * ND + ch * 64 + c * 8);
        }
        cp_commit();
    };

    // x LDG: thread owns rows (row0, row0+8), cols ds*16 + 4q .. +3 per chunk
    const float* xb = x + row0 * ND + q * 4;

    // ---- prologue ----
#pragma unroll
    for (int ds = 0; ds < 4; ds++) {
        xr[0][ds][0] = *(const float4*)(xb + ds * 16);
        xr[0][ds][1] = *(const float4*)(xb + ds * 16 + 8 * ND);
    }
    ldw(0, 0);
    ldw(1, 1);
#pragma unroll
    for (int ds = 0; ds < 4; ds++) {
        xr[1][ds][0] = *(const float4*)(xb + 64 + ds * 16);
        xr[1][ds][1] = *(const float4*)(xb + 64 + ds * 16 + 8 * ND);
    }
    cp_wait<1>();
    __syncthreads();

    // ---- main loop: ch unrolled by 2 so buffer indices are literals ----
    auto body = [&](int ch, int cb) {
#pragma unroll
        for (int ds = 0; ds < 4; ds++) {
            float4 f0 = xr[cb][ds][0];
            float4 f1 = xr[cb][ds][1];
            ss0 += f0.x * f0.x + f0.y * f0.y + f0.z * f0.z + f0.w * f0.w;
            ss1 += f1.x * f1.x + f1.y * f1.y + f1.z * f1.z + f1.w * f1.w;
            unsigned a0 = packbf(f0.x, f0.y), a2 = packbf(f0.z, f0.w);
            unsigned a1 = packbf(f1.x, f1.y), a3 = packbf(f1.z, f1.w);
            {   // raw bf16 out (natural order) for k_vlad
                __nv_bfloat16* gx = g_x16 + row0 * ND + ch * 64 + ds * 16 + q * 4;
                uint2 u0; u0.x = a0; u0.y = a2;
                uint2 u1; u1.x = a1; u1.y = a3;
                *(uint2*)gx            = u0;
                *(uint2*)(gx + 8 * ND) = u1;
            }
#pragma unroll
            for (int nt = 0; nt < 8; nt += 2) {
                unsigned b0, b1, b2, b3;
                int r = nt * 8 + (lane & 7) + ((lane >> 4) & 1) * 8;
                int c = ds * 16 + ((lane >> 3) & 1) * 8;
                ldsm_x4(b0, b1, b2, b3, s2u(wt[cb] + r * 72 + c));
                mma16816(acc[nt],     a0, a1, a2, a3, b0, b1);
                mma16816(acc[nt + 1], a0, a1, a2, a3, b2, b3);
            }
        }
        if (ch + 2 < 16) {
#pragma unroll
            for (int ds = 0; ds < 4; ds++) {
                xr[cb][ds][0] = *(const float4*)(xb + (ch + 2) * 64 + ds * 16);
                xr[cb][ds][1] = *(const float4*)(xb + (ch + 2) * 64 + ds * 16 + 8 * ND);
            }
        }
        __syncthreads();                 // all reads of wt[cb] complete
        if (ch + 2 < 16) { ldw(ch + 2, cb); cp_wait<1>(); }
        else             cp_wait<0>();
        __syncthreads();                 // wt writes visible
    };
    for (int ch2 = 0; ch2 < 16; ch2 += 2) {
        body(ch2,     0);
        body(ch2 + 1, 1);
    }

    // ---- row sum-of-squares: reduce over the 4 q-lanes ----
    ss0 += __shfl_xor_sync(0xffffffffu, ss0, 1);
    ss0 += __shfl_xor_sync(0xffffffffu, ss0, 2);
    ss1 += __shfl_xor_sync(0xffffffffu, ss1, 1);
    ss1 += __shfl_xor_sync(0xffffffffu, ss1, 2);
    if (q == 0) {
        ssrow[ar + gr]     = ss0;
        ssrow[ar + gr + 8] = ss1;
    }
    // ---- dump logits ----
#pragma unroll
    for (int nt = 0; nt < 8; nt++) {
        int r0 = ar + (lane >> 2);
        int c0 = nt * 8 + 2 * (lane & 3);
        lg[r0 * 66 + c0]           = acc[nt][0];
        lg[r0 * 66 + c0 + 1]       = acc[nt][1];
        lg[(r0 + 8) * 66 + c0]     = acc[nt][2];
        lg[(r0 + 8) * 66 + c0 + 1] = acc[nt][3];
    }
    __syncthreads();

    // ---- softmax: each warp does its 16 rows; lane owns cols (2l, 2l+1) ----
    float s0 = 0.f, s1 = 0.f;
    const int c0 = 2 * lane, c1 = 2 * lane + 1;
#pragma unroll 1
    for (int r = 0; r < 16; r++) {
        int rr = ar + r;
        float inv = 1.0f / fmaxf(sqrtf(ssrow[rr]), 1e-12f);
        float v0 = lg[rr * 66 + c0] * inv, v1 = lg[rr * 66 + c1] * inv;
        float mx = fmaxf(v0, v1);
#pragma unroll
        for (int o = 16; o > 0; o >>= 1) mx = fmaxf(mx, __shfl_xor_sync(0xffffffffu, mx, o));
        float e0 = expf(v0 - mx), e1 = expf(v1 - mx);
        float sm = e0 + e1;
#pragma unroll
        for (int o = 16; o > 0; o >>= 1) sm += __shfl_xor_sync(0xffffffffu, sm, o);
        float is = 1.0f / sm;
        float p0 = e0 * is, p1 = e1 * is;
        s0 += p0; s1 += p1;
        __nv_bfloat162 h;                    // store p * inv_m  (normalization folded in)
        h.x = __float2bfloat16_rn(p0 * inv);
        h.y = __float2bfloat16_rn(p1 * inv);
        ((__nv_bfloat162*)(g_a + (size_t)(m0 + rr) * NK))[lane] = h;
    }
    atomicAdd(&sas[c0], s0);
    atomicAdd(&sas[c1], s1);
    __syncthreads();
    if (tid < 64) atomicAdd(&g_asum[b * NK + tid], sas[tid]);
}

// ============ kernel: vlad partial[z][b] = A'(b, z-half)^T @ X(b, z-half) ============
// grid (8 d-tiles, 32 b, 2 m-splits); block computes [64 k x 128 d] over M=1024,
// 2-stage cp.async double buffering; B-side ldsm merged to x4t (2 nt per load).
#define VL_SMEM 53248
__global__ __launch_bounds__(256) void k_vlad() {
    extern __shared__ __align__(16) unsigned char dsm[];
    __nv_bfloat16* at[2] = { (__nv_bfloat16*)dsm,           (__nv_bfloat16*)(dsm + 9216) };
    __nv_bfloat16* xt[2] = { (__nv_bfloat16*)(dsm + 18432), (__nv_bfloat16*)(dsm + 35840) };

    const int tid = threadIdx.x, lane = tid & 31, warp = tid >> 5;
    const int b  = blockIdx.y;
    const int z  = blockIdx.z;
    const int d0 = blockIdx.x * 128;
    const int wk = (warp & 3) * 16;     // k-row base for this warp
    const int wd = (warp >> 2) * 64;    // d-col base within tile

    const size_t rowbase = (size_t)b * NM + (size_t)z * (NM / 2);

    float acc[8][4];
#pragma unroll
    for (int i = 0; i < 8; i++)
#pragma unroll
        for (int j = 0; j < 4; j++) acc[i][j] = 0.f;

    auto issue = [&](int mc, int s) {
        const size_t mrow = rowbase + mc * 64;
#pragma unroll
        for (int it = 0; it < 2; it++) {     // a tile: 64 m x 64 k
            int idx = tid + it * 256;
            int r = idx >> 3, c = idx & 7;
            cp16(s2u(at[s] + r * 72 + c * 8), g_a + (mrow + r) * NK + c * 8);
        }
#pragma unroll
        for (int it = 0; it < 4; it++) {     // x tile: 64 m x 128 d
            int idx = tid + it * 256;
            int r = idx >> 4, c = idx & 15;
            cp16(s2u(xt[s] + r * 136 + c * 8), g_x16 + (mrow + r) * ND + d0 + c * 8);
        }
        cp_commit();
    };

    issue(0, 0);
    for (int mc = 0; mc < 16; mc++) {
        if (mc + 1 < 16) { issue(mc + 1, (mc + 1) & 1); cp_wait<1>(); }
        else             { cp_wait<0>(); }
        __syncthreads();
        const int s = mc & 1;
#pragma unroll
        for (int ms = 0; ms < 4; ms++) {
            int mb = ms * 16;
            unsigned a0, a1, a2, a3;
            {   // A = a^T (k x m) from [m][k] storage -> ldmatrix.trans
                int i = lane & 7;
                int r = mb + i + ((lane >> 4) & 1) * 8;
                int c = wk + ((lane >> 3) & 1) * 8;
                ldsm_x4t(a0, a1, a2, a3, s2u(at[s] + r * 72 + c));
            }
#pragma unroll
            for (int nt = 0; nt < 8; nt += 2) {
                unsigned b0, b1, b2, b3;
                int r = mb + (lane & 7) + ((lane >> 3) & 1) * 8;
                int c = wd + nt * 8 + ((lane >> 4) & 1) * 8;
                ldsm_x4t(b0, b1, b2, b3, s2u(xt[s] + r * 136 + c));
                mma16816(acc[nt],     a0, a1, a2, a3, b0, b1);
                mma16816(acc[nt + 1], a0, a1, a2, a3, b2, b3);
            }
        }
        __syncthreads();
    }

    float* vb = g_vraw + ((size_t)z * NB + b) * NK * ND;
#pragma unroll
    for (int nt = 0; nt < 8; nt++) {
        int k0 = wk + (lane >> 2);
        int dd = d0 + wd + nt * 8 + 2 * (lane & 3);
        *(float2*)(vb + (size_t)k0 * ND + dd)       = make_float2(acc[nt][0], acc[nt][1]);
        *(float2*)(vb + (size_t)(k0 + 8) * ND + dd) = make_float2(acc[nt][2], acc[nt][3]);
    }
}

// ---------------- kernel: centroid subtract + intra-norm + global(1/8) ----------------
__global__ __launch_bounds__(256) void k_final(const float* __restrict__ cent,
                                               float* __restrict__ out) {
    const int bk = blockIdx.x;           // b*64 + k
    const int k  = bk & 63;
    const int tid = threadIdx.x, lane = tid & 31, warp = tid >> 5;
    const float* vr0 = g_vraw + (size_t)bk * ND;
    const float* vr1 = g_vraw + (size_t)NB * NK * ND + (size_t)bk * ND;
    const float* cp = cent + (size_t)k * ND;
    const float as = g_asum[bk];
    float v[4];
    float ss = 0.f;
#pragma unroll
    for (int i = 0; i < 4; i++) {
        int d = tid + i * 256;
        v[i] = vr0[d] + vr1[d] - as * cp[d];
        ss += v[i] * v[i];
    }
#pragma unroll
    for (int o = 16; o > 0; o >>= 1) ss += __shfl_xor_sync(0xffffffffu, ss, o);
    __shared__ float red[8];
    if (lane == 0) red[warp] = ss;
    __syncthreads();
    float tot = red[0] + red[1] + red[2] + red[3] + red[4] + red[5] + red[6] + red[7];
    // intra-normalize; global norm is exactly sqrt(64)=8 after intra-normalization
    float inv = 0.125f / fmaxf(sqrtf(tot), 1e-12f);
    float* op = out + (size_t)bk * ND;
#pragma unroll
    for (int i = 0; i < 4; i++) op[tid + i * 256] = v[i] * inv;
}

// ---------------- launch ----------------
extern "C" void kernel_launch(void* const* d_in, const int* in_sizes, int n_in,
                              void* d_out, int out_size) {
    const float* x    = (const float*)d_in[0];
    const float* W    = (const float*)d_in[1];
    const float* cent = (const float*)d_in[2];
    float* out = (float*)d_out;

    static int configured = 0;
    if (!configured) {
        cudaFuncSetAttribute(k_nl,   cudaFuncAttributeMaxDynamicSharedMemorySize, NL_SMEM);
        cudaFuncSetAttribute(k_vlad, cudaFuncAttributeMaxDynamicSharedMemorySize, VL_SMEM);
        configured = 1;
    }

    k_wconv<<<256, 256>>>(W);
    k_nl   <<<512, 256, NL_SMEM>>>(x);
    k_vlad <<<dim3(8, 32, 2), 256, VL_SMEM>>>();
    k_final<<<2048, 256>>>(cent, out);
}